// round 11
// baseline (speedup 1.0000x reference)
#include <cuda_runtime.h>
#include <cuda_bf16.h>
#include <math.h>

// ---------------------------------------------------------------------------
// AutoEncoder3D + symmetric Chamfer loss, fully fused on-device.
// B=2, D_IN=1024, SPACE=3, BOTT=64, G=64, N=G*1024=65536 per batch.
// ---------------------------------------------------------------------------

#define NEG_INF (__int_as_float(0xff800000))

// ---------------- packed f32x2 helpers (Blackwell FFMA2 path) ----------------
typedef unsigned long long u64t;
__device__ __forceinline__ u64t pk2(float lo, float hi) {
    u64t r; asm("mov.b64 %0, {%1, %2};" : "=l"(r) : "f"(lo), "f"(hi)); return r;
}
__device__ __forceinline__ void upk2(float& lo, float& hi, u64t v) {
    asm("mov.b64 {%0, %1}, %2;" : "=f"(lo), "=f"(hi) : "l"(v));
}
__device__ __forceinline__ u64t fma2(u64t a, u64t b, u64t c) {
    u64t d; asm("fma.rn.f32x2 %0, %1, %2, %3;" : "=l"(d) : "l"(a), "l"(b), "l"(c)); return d;
}
__device__ __forceinline__ u64t add2(u64t a, u64t b) {
    u64t d; asm("add.rn.f32x2 %0, %1, %2;" : "=l"(d) : "l"(a), "l"(b)); return d;
}

// ---------------- scratch (static __device__, no allocations) ---------------
__device__ float    g_h1part[16][2][512];    // e1 K-split partials
__device__ float    g_z[2][64];              // latent
__device__ float    g_d2t[512 * 128];        // decoder L2 activations, TRANSPOSED [k][row]
__device__ float    g_p3[8][128 * 3072];     // dec3 K-split partials
__device__ unsigned g_umax[2048];            // ordered-uint max_u per (b,m)
__device__ float    g_partN[512];            // per-block sum of max_u over n

// ordered-uint encoding for float atomicMax (monotone for all finite floats)
__device__ __forceinline__ unsigned enc_f(float f) {
    unsigned u = __float_as_uint(f);
    return (u & 0x80000000u) ? ~u : (u | 0x80000000u);
}
__device__ __forceinline__ float dec_f(unsigned u) {
    unsigned v = (u & 0x80000000u) ? (u & 0x7FFFFFFFu) : ~u;
    return __uint_as_float(v);
}

// ---------------- encoder layer 1: [B,3072] x [3072,512], K-split x16 -------
__global__ void k_e1(const float* __restrict__ x, const float* __restrict__ We1) {
    __shared__ float xs[192];
    const int tid = threadIdx.x;                 // 512
    const int b = blockIdx.x >> 4, kc = blockIdx.x & 15;

    if (blockIdx.x == 0) {                       // re-init umax each replay
        for (int i = tid; i < 2048; i += 512) g_umax[i] = 0u;
    }
    if (tid < 192) xs[tid] = x[b * 3072 + kc * 192 + tid];
    __syncthreads();

    const float* W = We1 + (size_t)(kc * 192) * 512 + tid;
    float a0 = 0.f, a1 = 0.f, a2 = 0.f, a3 = 0.f;
#pragma unroll 4
    for (int i = 0; i < 192; i += 4) {
        a0 = fmaf(xs[i + 0], W[(size_t)(i + 0) * 512], a0);
        a1 = fmaf(xs[i + 1], W[(size_t)(i + 1) * 512], a1);
        a2 = fmaf(xs[i + 2], W[(size_t)(i + 2) * 512], a2);
        a3 = fmaf(xs[i + 3], W[(size_t)(i + 3) * 512], a3);
    }
    g_h1part[kc][b][tid] = (a0 + a1) + (a2 + a3);
}

// ---------------- encoder layers 2+3 ----------------------------------------
__global__ void k_e23(const float* __restrict__ be1,
                      const float* __restrict__ We2, const float* __restrict__ be2,
                      const float* __restrict__ We3, const float* __restrict__ be3) {
    __shared__ float h1s[512];
    __shared__ float h2s[128];
    const int b = blockIdx.x, tid = threadIdx.x;     // 128 threads

    for (int i = tid; i < 512; i += 128) {
        float a = be1[i];
#pragma unroll
        for (int p = 0; p < 16; p++) a += g_h1part[p][b][i];
        h1s[i] = fmaxf(a, 0.f);
    }
    __syncthreads();

    {
        float c0 = 0.f, c1 = 0.f, c2 = 0.f, c3 = 0.f;
#pragma unroll 4
        for (int i = 0; i < 512; i += 4) {
            c0 = fmaf(h1s[i + 0], We2[(size_t)(i + 0) * 128 + tid], c0);
            c1 = fmaf(h1s[i + 1], We2[(size_t)(i + 1) * 128 + tid], c1);
            c2 = fmaf(h1s[i + 2], We2[(size_t)(i + 2) * 128 + tid], c2);
            c3 = fmaf(h1s[i + 3], We2[(size_t)(i + 3) * 128 + tid], c3);
        }
        h2s[tid] = fmaxf(((c0 + c1) + (c2 + c3)) + be2[tid], 0.f);
    }
    __syncthreads();

    if (tid < 64) {
        float a = be3[tid];
#pragma unroll 4
        for (int i = 0; i < 128; i++) a = fmaf(h2s[i], We3[(size_t)i * 64 + tid], a);
        g_z[b][tid] = fmaxf(a, 0.f);
    }
}

// ---------------- decoder layers 1+2: one block per (b,g) row ---------------
// Writes activations TRANSPOSED: g_d2t[k*128 + row].
__global__ void k_dec12(const float* __restrict__ grid,
                        const float* __restrict__ Wd1, const float* __restrict__ bd1,
                        const float* __restrict__ Wd2, const float* __restrict__ bd2) {
    __shared__ float zi[68];
    __shared__ float d1s[128];
    const int tid = threadIdx.x;                 // 128
    const int r = blockIdx.x, b = r >> 6, g = r & 63;

    if (tid < 64)       zi[tid] = g_z[b][tid];
    else if (tid < 67)  zi[tid] = grid[g * 3 + (tid - 64)];
    __syncthreads();

    float a = bd1[tid];
#pragma unroll
    for (int i = 0; i < 67; i++) a = fmaf(zi[i], Wd1[(size_t)i * 128 + tid], a);
    d1s[tid] = fmaxf(a, 0.f);
    __syncthreads();

    float c0 = bd2[tid], c1 = bd2[tid + 128], c2 = bd2[tid + 256], c3 = bd2[tid + 384];
#pragma unroll 8
    for (int i = 0; i < 128; i++) {
        const float h = d1s[i];
        const float* W = Wd2 + (size_t)i * 512 + tid;
        c0 = fmaf(h, W[0],   c0);
        c1 = fmaf(h, W[128], c1);
        c2 = fmaf(h, W[256], c2);
        c3 = fmaf(h, W[384], c3);
    }
    g_d2t[(size_t)(tid)       * 128 + r] = fmaxf(c0, 0.f);
    g_d2t[(size_t)(tid + 128) * 128 + r] = fmaxf(c1, 0.f);
    g_d2t[(size_t)(tid + 256) * 128 + r] = fmaxf(c2, 0.f);
    g_d2t[(size_t)(tid + 384) * 128 + r] = fmaxf(c3, 0.f);
}

// ---------------- decoder layer 3: 128x3072x512 GEMM, 8-way K-split ---------
// Grid: 768 blocks = 96 n-tiles x 8 K-chunks of 64. Block: 128 threads.
// Thread tile: 4 row-PAIRS (natural packed A from shared) x 4 cols (B stored
// pre-duplicated with XOR-swizzled 16B halves + row pad 72 -> conflict-free
// loads AND stores). Zero MOVs inner loop: 4 LDS.128 + 16 FFMA2 per kk.
__global__ void k_dec3(const float* __restrict__ Wd3) {
    __shared__ __align__(16) float As[32][132];   // [kk][row]
    __shared__ __align__(16) float Bs2[32][72];   // [kk][col dup, swizzled]
    const int tid = threadIdx.x;                  // 128
    const int nt = blockIdx.x % 96, kc = blockIdx.x / 96;
    const int n0 = nt * 32, kbase = kc * 64;
    const int tx = tid & 7, ty = tid >> 3;        // tx: 4-col group, ty: 8-row group
    const int boff_lo = tx * 8 + (tx & 4);        // {b0,b0,b1,b1}
    const int boff_hi = tx * 8 + 4 - (tx & 4);    // {b2,b2,b3,b3}

    u64t acc[4][4];                               // [row-pair][col]
#pragma unroll
    for (int p = 0; p < 4; p++)
#pragma unroll
        for (int c = 0; c < 4; c++) acc[p][c] = 0ull;

    for (int ks = 0; ks < 64; ks += 32) {
        // A tile: 32k x 128 rows, 8 float4 per thread, coalesced
#pragma unroll
        for (int j = 0; j < 8; j++) {
            const int idx = tid + j * 128;
            const int kk = idx >> 5, r4 = idx & 31;
            *(float4*)&As[kk][r4 * 4] =
                *(const float4*)&g_d2t[(size_t)(kbase + ks + kk) * 128 + r4 * 4];
        }
        // B tile: 32k x 32 cols, duplicated {b,b}, swizzled halves
#pragma unroll
        for (int j = 0; j < 2; j++) {
            const int idx = tid + j * 128;
            const int kk = idx >> 3, c4 = idx & 7;
            const float4 v = *(const float4*)&Wd3[(size_t)(kbase + ks + kk) * 3072 + n0 + c4 * 4];
            *(float4*)&Bs2[kk][c4 * 8 + (c4 & 4)]     = make_float4(v.x, v.x, v.y, v.y);
            *(float4*)&Bs2[kk][c4 * 8 + 4 - (c4 & 4)] = make_float4(v.z, v.z, v.w, v.w);
        }
        __syncthreads();
#pragma unroll
        for (int kk = 0; kk < 32; kk++) {
            const ulonglong2 aA  = *(const ulonglong2*)&As[kk][ty * 8];      // {r0,r1},{r2,r3}
            const ulonglong2 aB  = *(const ulonglong2*)&As[kk][ty * 8 + 4];  // {r4,r5},{r6,r7}
            const ulonglong2 b01 = *(const ulonglong2*)&Bs2[kk][boff_lo];    // {b0,b0},{b1,b1}
            const ulonglong2 b23 = *(const ulonglong2*)&Bs2[kk][boff_hi];    // {b2,b2},{b3,b3}
            acc[0][0] = fma2(aA.x, b01.x, acc[0][0]); acc[0][1] = fma2(aA.x, b01.y, acc[0][1]);
            acc[0][2] = fma2(aA.x, b23.x, acc[0][2]); acc[0][3] = fma2(aA.x, b23.y, acc[0][3]);
            acc[1][0] = fma2(aA.y, b01.x, acc[1][0]); acc[1][1] = fma2(aA.y, b01.y, acc[1][1]);
            acc[1][2] = fma2(aA.y, b23.x, acc[1][2]); acc[1][3] = fma2(aA.y, b23.y, acc[1][3]);
            acc[2][0] = fma2(aB.x, b01.x, acc[2][0]); acc[2][1] = fma2(aB.x, b01.y, acc[2][1]);
            acc[2][2] = fma2(aB.x, b23.x, acc[2][2]); acc[2][3] = fma2(aB.x, b23.y, acc[2][3]);
            acc[3][0] = fma2(aB.y, b01.x, acc[3][0]); acc[3][1] = fma2(aB.y, b01.y, acc[3][1]);
            acc[3][2] = fma2(aB.y, b23.x, acc[3][2]); acc[3][3] = fma2(aB.y, b23.y, acc[3][3]);
        }
        __syncthreads();
    }

    float* P = g_p3[kc];
#pragma unroll
    for (int p = 0; p < 4; p++) {
        float l0, h0, l1, h1, l2, h2, l3, h3;
        upk2(l0, h0, acc[p][0]);
        upk2(l1, h1, acc[p][1]);
        upk2(l2, h2, acc[p][2]);
        upk2(l3, h3, acc[p][3]);
        const int r0 = ty * 8 + 2 * p;
        *(float4*)&P[(size_t)r0 * 3072 + n0 + tx * 4]       = make_float4(l0, l1, l2, l3);
        *(float4*)&P[(size_t)(r0 + 1) * 3072 + n0 + tx * 4] = make_float4(h0, h1, h2, h3);
    }
}

// ---------------- fused partial-sum + bias + tanh + symmetric Chamfer -------
// u = s.y - 0.5|s|^2 - 0.5|y|^2  =>  min d2 = -2 * max u, both directions.
// FIX (R11): phase 1 now covers ALL 768 floats (192 float4 chunks with 128
// threads -> strided loop). Previously `if (tid < 192)` with 128 threads left
// ysc[512..767] uninitialized -> 1/3 of generated points were smem garbage.
#define CH_NS 256
__global__ void k_chamfer(const float* __restrict__ x, const float* __restrict__ bd3) {
    __shared__ __align__(16) float ys2[CH_NS][8]; // {yx,yx,yy,yy,yz,yz,yw,yw}
    __shared__ __align__(16) float ysc[CH_NS * 3];
    __shared__ float mred[32][133];
    __shared__ float pw2[32][4];
    const int tid  = threadIdx.x;                 // 128
    const int lane = tid & 31, w = tid >> 5;
    const int bidx = blockIdx.x;                  // 512 blocks
    const int b = bidx >> 8, s = bidx & 255;
    const int n0 = s * CH_NS;

    // --- phase 1: Y = tanh(sum of 8 K-split partials + bias) for 256 points -
    {
        const int gf0 = b * 196608 + n0 * 3;           // flat float base
        const int col0 = (n0 & 1023) * 3;              // bias column base
        for (int o4 = tid; o4 < 192; o4 += 128) {      // FULL 768-float coverage
            const int o = o4 * 4;
            float4 sacc = *(const float4*)&g_p3[0][gf0 + o];
#pragma unroll
            for (int p = 1; p < 8; p++) {
                const float4 q = *(const float4*)&g_p3[p][gf0 + o];
                sacc.x += q.x; sacc.y += q.y; sacc.z += q.z; sacc.w += q.w;
            }
            const float4 bb = *(const float4*)&bd3[col0 + o];
            sacc.x = tanhf(sacc.x + bb.x);
            sacc.y = tanhf(sacc.y + bb.y);
            sacc.z = tanhf(sacc.z + bb.z);
            sacc.w = tanhf(sacc.w + bb.w);
            *(float4*)&ysc[o] = sacc;
        }
    }
    __syncthreads();
    for (int nn = tid; nn < CH_NS; nn += 128) {
        const float yx = ysc[nn * 3 + 0];
        const float yy = ysc[nn * 3 + 1];
        const float yz = ysc[nn * 3 + 2];
        const float yw = -0.5f * (yx * yx + yy * yy + yz * yz);
        *(float4*)&ys2[nn][0] = make_float4(yx, yx, yy, yy);
        *(float4*)&ys2[nn][4] = make_float4(yz, yz, yw, yw);
    }

    // --- phase 2: per-lane targets, 8 m's as 4 packed pairs ------------------
    u64t sx2[4], sy2[4], sz2[4], hs2[4];
    float mBlo[4], mBhi[4];
    const float* xb = x + (size_t)b * 3072;
#pragma unroll
    for (int g = 0; g < 4; g++) {
        const int m0 = w * 256 + (2 * g) * 32 + lane;
        const int m1 = m0 + 32;
        const float ax = xb[m0 * 3 + 0], ay = xb[m0 * 3 + 1], az = xb[m0 * 3 + 2];
        const float cx = xb[m1 * 3 + 0], cy = xb[m1 * 3 + 1], cz = xb[m1 * 3 + 2];
        sx2[g] = pk2(ax, cx);
        sy2[g] = pk2(ay, cy);
        sz2[g] = pk2(az, cz);
        hs2[g] = pk2(-0.5f * (ax * ax + ay * ay + az * az),
                     -0.5f * (cx * cx + cy * cy + cz * cz));
        mBlo[g] = NEG_INF; mBhi[g] = NEG_INF;
    }
    __syncthreads();

    float sum_n = 0.f;                            // meaningful for tid < 32
    for (int c0 = 0; c0 < CH_NS; c0 += 32) {
#pragma unroll 2
        for (int k = 0; k < 32; k++) {
            const int nn = c0 + k;
            const ulonglong2 yA = *(const ulonglong2*)&ys2[nn][0];  // yx2, yy2
            const ulonglong2 yB = *(const ulonglong2*)&ys2[nn][4];  // yz2, yw2
            float ul[4], uh[4];
#pragma unroll
            for (int g = 0; g < 4; g++) {
                u64t t = fma2(sx2[g], yA.x, hs2[g]);
                t = fma2(sy2[g], yA.y, t);
                t = fma2(sz2[g], yB.x, t);
                t = add2(t, yB.y);
                upk2(ul[g], uh[g], t);
                mBlo[g] = fmaxf(mBlo[g], ul[g]);
                mBhi[g] = fmaxf(mBhi[g], uh[g]);
            }
            mred[k][tid] = fmaxf(fmaxf(fmaxf(ul[0], uh[0]), fmaxf(ul[1], uh[1])),
                                 fmaxf(fmaxf(ul[2], uh[2]), fmaxf(ul[3], uh[3])));
        }
        __syncthreads();
        // cooperative reduce: 4 threads per nn, 32 lanes each
        {
            const int nnl = tid & 31, part = tid >> 5;
            const float* row = &mred[nnl][part * 32];
            float sm = row[0];
#pragma unroll
            for (int j = 1; j < 32; j++) sm = fmaxf(sm, row[j]);
            pw2[nnl][part] = sm;
        }
        __syncthreads();
        if (tid < 32)
            sum_n += fmaxf(fmaxf(pw2[tid][0], pw2[tid][1]),
                           fmaxf(pw2[tid][2], pw2[tid][3]));
        __syncthreads();
    }

    if (tid < 32) {
#pragma unroll
        for (int off = 16; off; off >>= 1)
            sum_n += __shfl_xor_sync(0xffffffffu, sum_n, off);
        if (tid == 0) g_partN[bidx] = sum_n;
    }

    // per-m running max over this block's n-slice -> global
#pragma unroll
    for (int g = 0; g < 4; g++) {
        const int m0 = w * 256 + (2 * g) * 32 + lane;
        atomicMax(&g_umax[b * 1024 + m0],      enc_f(mBlo[g]));
        atomicMax(&g_umax[b * 1024 + m0 + 32], enc_f(mBhi[g]));
    }
}

// ---------------- final reduction -------------------------------------------
__global__ void k_final(float* __restrict__ out) {
    __shared__ float red[8];
    const int tid = threadIdx.x;                 // 256
    float loc = 0.f;
    for (int i = tid; i < 2048; i += 256) loc += dec_f(g_umax[i]);
    for (int i = tid; i < 512; i += 256)  loc += g_partN[i];
#pragma unroll
    for (int off = 16; off; off >>= 1)
        loc += __shfl_xor_sync(0xffffffffu, loc, off);
    if ((tid & 31) == 0) red[tid >> 5] = loc;
    __syncthreads();
    if (tid == 0) {
        float t = 0.f;
#pragma unroll
        for (int i = 0; i < 8; i++) t += red[i];
        out[0] = -2.f * t;
    }
}

// ---------------------------------------------------------------------------
extern "C" void kernel_launch(void* const* d_in, const int* in_sizes, int n_in,
                              void* d_out, int out_size) {
    const float* x    = (const float*)d_in[0];
    const float* grid = (const float*)d_in[1];
    const float* We1  = (const float*)d_in[2];
    const float* be1  = (const float*)d_in[3];
    const float* We2  = (const float*)d_in[4];
    const float* be2  = (const float*)d_in[5];
    const float* We3  = (const float*)d_in[6];
    const float* be3  = (const float*)d_in[7];
    const float* Wd1  = (const float*)d_in[8];
    const float* bd1  = (const float*)d_in[9];
    const float* Wd2  = (const float*)d_in[10];
    const float* bd2  = (const float*)d_in[11];
    const float* Wd3  = (const float*)d_in[12];
    const float* bd3  = (const float*)d_in[13];
    float* out = (float*)d_out;

    k_e1<<<32, 512>>>(x, We1);
    k_e23<<<2, 128>>>(be1, We2, be2, We3, be3);
    k_dec12<<<128, 128>>>(grid, Wd1, bd1, Wd2, bd2);
    k_dec3<<<768, 128>>>(Wd3);
    k_chamfer<<<512, 128>>>(x, bd3);
    k_final<<<1, 256>>>(out);
}

// round 12
// speedup vs baseline: 1.6904x; 1.6904x over previous
#include <cuda_runtime.h>
#include <cuda_bf16.h>
#include <math.h>

// ---------------------------------------------------------------------------
// AutoEncoder3D + symmetric Chamfer loss, fully fused on-device.
// B=2, D_IN=1024, SPACE=3, BOTT=64, G=64, N=G*1024=65536 per batch.
// ---------------------------------------------------------------------------

#define NEG_INF (__int_as_float(0xff800000))

// ---------------- packed f32x2 helpers (Blackwell FFMA2 path) ----------------
typedef unsigned long long u64t;
__device__ __forceinline__ u64t pk2(float lo, float hi) {
    u64t r; asm("mov.b64 %0, {%1, %2};" : "=l"(r) : "f"(lo), "f"(hi)); return r;
}
__device__ __forceinline__ void upk2(float& lo, float& hi, u64t v) {
    asm("mov.b64 {%0, %1}, %2;" : "=f"(lo), "=f"(hi) : "l"(v));
}
__device__ __forceinline__ u64t fma2(u64t a, u64t b, u64t c) {
    u64t d; asm("fma.rn.f32x2 %0, %1, %2, %3;" : "=l"(d) : "l"(a), "l"(b), "l"(c)); return d;
}
__device__ __forceinline__ u64t add2(u64t a, u64t b) {
    u64t d; asm("add.rn.f32x2 %0, %1, %2;" : "=l"(d) : "l"(a), "l"(b)); return d;
}

// ---------------- scratch (static __device__, no allocations) ---------------
__device__ float    g_h1part[16][2][512];    // e1 K-split partials
__device__ float    g_h2part[8][2][128];     // e2 K-split partials
__device__ float    g_d2t[512 * 128];        // decoder L2 activations, TRANSPOSED [k][row]
__device__ float    g_p3[8][128 * 3072];     // dec3 K-split partials
__device__ unsigned g_umax[2048];            // ordered-uint max_u per (b,m)
__device__ float    g_partN[512];            // per-block sum of max_u over n
__device__ unsigned g_done;                  // chamfer completion counter

// ordered-uint encoding for float atomicMax (monotone for all finite floats)
__device__ __forceinline__ unsigned enc_f(float f) {
    unsigned u = __float_as_uint(f);
    return (u & 0x80000000u) ? ~u : (u | 0x80000000u);
}
__device__ __forceinline__ float dec_f(unsigned u) {
    unsigned v = (u & 0x80000000u) ? (u & 0x7FFFFFFFu) : ~u;
    return __uint_as_float(v);
}

// ---------------- encoder layer 1: [B,3072] x [3072,512], K-split x16 -------
__global__ void k_e1(const float* __restrict__ x, const float* __restrict__ We1) {
    __shared__ float xs[192];
    const int tid = threadIdx.x;                 // 512
    const int b = blockIdx.x >> 4, kc = blockIdx.x & 15;

    if (blockIdx.x == 0) {                       // re-init per replay
        for (int i = tid; i < 2048; i += 512) g_umax[i] = 0u;
        if (tid == 0) g_done = 0u;
    }
    if (tid < 192) xs[tid] = x[b * 3072 + kc * 192 + tid];
    __syncthreads();

    const float* W = We1 + (size_t)(kc * 192) * 512 + tid;
    float a0 = 0.f, a1 = 0.f, a2 = 0.f, a3 = 0.f;
#pragma unroll 16
    for (int i = 0; i < 192; i += 4) {
        a0 = fmaf(xs[i + 0], W[(size_t)(i + 0) * 512], a0);
        a1 = fmaf(xs[i + 1], W[(size_t)(i + 1) * 512], a1);
        a2 = fmaf(xs[i + 2], W[(size_t)(i + 2) * 512], a2);
        a3 = fmaf(xs[i + 3], W[(size_t)(i + 3) * 512], a3);
    }
    g_h1part[kc][b][tid] = (a0 + a1) + (a2 + a3);
}

// ---------------- encoder layer 2 (K-split x8): h2 partials -----------------
// Grid 16 = (b, kc in 8). Each block: h1 chunk of 64 -> partial h2[128].
__global__ void k_e2(const float* __restrict__ be1, const float* __restrict__ We2) {
    __shared__ float h1c[64];
    const int tid = threadIdx.x;                 // 128
    const int b = blockIdx.x >> 3, kc = blockIdx.x & 7;

    if (tid < 64) {
        const int col = kc * 64 + tid;
        float a = be1[col];
#pragma unroll
        for (int p = 0; p < 16; p++) a += g_h1part[p][b][col];
        h1c[tid] = fmaxf(a, 0.f);
    }
    __syncthreads();

    const float* W = We2 + (size_t)(kc * 64) * 128 + tid;
    float c0 = 0.f, c1 = 0.f, c2 = 0.f, c3 = 0.f;
#pragma unroll
    for (int k = 0; k < 64; k += 4) {
        c0 = fmaf(h1c[k + 0], W[(size_t)(k + 0) * 128], c0);
        c1 = fmaf(h1c[k + 1], W[(size_t)(k + 1) * 128], c1);
        c2 = fmaf(h1c[k + 2], W[(size_t)(k + 2) * 128], c2);
        c3 = fmaf(h1c[k + 3], W[(size_t)(k + 3) * 128], c3);
    }
    g_h2part[kc][b][tid] = (c0 + c1) + (c2 + c3);
}

// ---------------- decoder: e-layer3 + dec layers 1+2, one block per (b,g) ---
// Prologue combines h2 partials, computes latent z (128x64 GEMV, We3 L2-hot),
// then decoder layers 1+2. Writes activations TRANSPOSED: g_d2t[k*128 + row].
__global__ void k_dec12(const float* __restrict__ grid,
                        const float* __restrict__ be2,
                        const float* __restrict__ We3, const float* __restrict__ be3,
                        const float* __restrict__ Wd1, const float* __restrict__ bd1,
                        const float* __restrict__ Wd2, const float* __restrict__ bd2) {
    __shared__ float h2s[128];
    __shared__ float zi[68];
    __shared__ float d1s[128];
    const int tid = threadIdx.x;                 // 128
    const int r = blockIdx.x, b = r >> 6, g = r & 63;

    {
        float a = be2[tid];
#pragma unroll
        for (int p = 0; p < 8; p++) a += g_h2part[p][b][tid];
        h2s[tid] = fmaxf(a, 0.f);
    }
    __syncthreads();

    if (tid < 64) {
        float a = be3[tid];
#pragma unroll 8
        for (int i = 0; i < 128; i++) a = fmaf(h2s[i], We3[(size_t)i * 64 + tid], a);
        zi[tid] = fmaxf(a, 0.f);
    } else if (tid < 67) {
        zi[tid] = grid[g * 3 + (tid - 64)];
    }
    __syncthreads();

    float a = bd1[tid];
#pragma unroll
    for (int i = 0; i < 67; i++) a = fmaf(zi[i], Wd1[(size_t)i * 128 + tid], a);
    d1s[tid] = fmaxf(a, 0.f);
    __syncthreads();

    float c0 = bd2[tid], c1 = bd2[tid + 128], c2 = bd2[tid + 256], c3 = bd2[tid + 384];
#pragma unroll 8
    for (int i = 0; i < 128; i++) {
        const float h = d1s[i];
        const float* W = Wd2 + (size_t)i * 512 + tid;
        c0 = fmaf(h, W[0],   c0);
        c1 = fmaf(h, W[128], c1);
        c2 = fmaf(h, W[256], c2);
        c3 = fmaf(h, W[384], c3);
    }
    g_d2t[(size_t)(tid)       * 128 + r] = fmaxf(c0, 0.f);
    g_d2t[(size_t)(tid + 128) * 128 + r] = fmaxf(c1, 0.f);
    g_d2t[(size_t)(tid + 256) * 128 + r] = fmaxf(c2, 0.f);
    g_d2t[(size_t)(tid + 384) * 128 + r] = fmaxf(c3, 0.f);
}

// ---------------- decoder layer 3: 128x3072x512 GEMM, 8-way K-split ---------
// Grid: 768 blocks = 96 n-tiles x 8 K-chunks of 64. Block: 128 threads.
// Row-pair FFMA2 accumulators: A loads are naturally packed (broadcast-phase
// LDS.128 from plain As), B is plain in shared; only 4 pk2 dup-MOVs per kk.
// Inner loop: 3 LDS.128 + 4 pk2 + 16 FFMA2 = 23 issues/kk.
__global__ void k_dec3(const float* __restrict__ Wd3) {
    __shared__ __align__(16) float As[16][132];   // [kk][row]
    __shared__ __align__(16) float Bs[16][32];    // [kk][col]
    const int tid = threadIdx.x;                  // 128
    const int nt = blockIdx.x % 96, kc = blockIdx.x / 96;
    const int n0 = nt * 32, kbase = kc * 64;
    const int tx = tid & 7, ty = tid >> 3;        // tx: 4-col group, ty: 8-row group

    u64t acc[4][4];                               // [row-pair][col]
#pragma unroll
    for (int p = 0; p < 4; p++)
#pragma unroll
        for (int c = 0; c < 4; c++) acc[p][c] = 0ull;

    const int kkA = tid >> 5, r4 = tid & 31;      // A fill
    const int kkB = tid >> 3, c4 = tid & 7;       // B fill

    for (int ks = 0; ks < 64; ks += 16) {
        // A tile: 16k x 128 rows (coalesced from transposed activations)
#pragma unroll
        for (int j = 0; j < 4; j++) {
            const int kk = kkA + j * 4;
            *(float4*)&As[kk][r4 * 4] =
                *(const float4*)&g_d2t[(size_t)(kbase + ks + kk) * 128 + r4 * 4];
        }
        // B tile: 16k x 32 cols (coalesced)
        *(float4*)&Bs[kkB][c4 * 4] =
            *(const float4*)&Wd3[(size_t)(kbase + ks + kkB) * 3072 + n0 + c4 * 4];
        __syncthreads();
#pragma unroll
        for (int kk = 0; kk < 16; kk++) {
            const ulonglong2 aA = *(const ulonglong2*)&As[kk][ty * 8];      // {r0,r1},{r2,r3}
            const ulonglong2 aB = *(const ulonglong2*)&As[kk][ty * 8 + 4];  // {r4,r5},{r6,r7}
            const float4 bv = *(const float4*)&Bs[kk][tx * 4];
            const u64t b0 = pk2(bv.x, bv.x), b1 = pk2(bv.y, bv.y);
            const u64t b2 = pk2(bv.z, bv.z), b3 = pk2(bv.w, bv.w);
            acc[0][0] = fma2(aA.x, b0, acc[0][0]); acc[0][1] = fma2(aA.x, b1, acc[0][1]);
            acc[0][2] = fma2(aA.x, b2, acc[0][2]); acc[0][3] = fma2(aA.x, b3, acc[0][3]);
            acc[1][0] = fma2(aA.y, b0, acc[1][0]); acc[1][1] = fma2(aA.y, b1, acc[1][1]);
            acc[1][2] = fma2(aA.y, b2, acc[1][2]); acc[1][3] = fma2(aA.y, b3, acc[1][3]);
            acc[2][0] = fma2(aB.x, b0, acc[2][0]); acc[2][1] = fma2(aB.x, b1, acc[2][1]);
            acc[2][2] = fma2(aB.x, b2, acc[2][2]); acc[2][3] = fma2(aB.x, b3, acc[2][3]);
            acc[3][0] = fma2(aB.y, b0, acc[3][0]); acc[3][1] = fma2(aB.y, b1, acc[3][1]);
            acc[3][2] = fma2(aB.y, b2, acc[3][2]); acc[3][3] = fma2(aB.y, b3, acc[3][3]);
        }
        __syncthreads();
    }

    float* P = g_p3[kc];
#pragma unroll
    for (int p = 0; p < 4; p++) {
        float l0, h0, l1, h1, l2, h2, l3, h3;
        upk2(l0, h0, acc[p][0]);
        upk2(l1, h1, acc[p][1]);
        upk2(l2, h2, acc[p][2]);
        upk2(l3, h3, acc[p][3]);
        const int r0 = ty * 8 + 2 * p;
        *(float4*)&P[(size_t)r0 * 3072 + n0 + tx * 4]       = make_float4(l0, l1, l2, l3);
        *(float4*)&P[(size_t)(r0 + 1) * 3072 + n0 + tx * 4] = make_float4(h0, h1, h2, h3);
    }
}

// ---------------- fused partial-sum + bias + tanh + symmetric Chamfer -------
// u = s.y - 0.5|s|^2 - 0.5|y|^2  =>  min d2 = -2 * max u, both directions.
// Last-block-done pattern performs the final global reduction (deterministic:
// atomicMax results are order-independent; the sum order is fixed).
#define CH_NS 256
__global__ void k_chamfer(const float* __restrict__ x, const float* __restrict__ bd3,
                          float* __restrict__ out) {
    __shared__ __align__(16) float ys2[CH_NS][8]; // {yx,yx,yy,yy,yz,yz,yw,yw}
    __shared__ __align__(16) float ysc[CH_NS * 3];
    __shared__ float mred[32][133];
    __shared__ float pw2[32][4];
    __shared__ float red2[4];
    __shared__ unsigned isLast;
    const int tid  = threadIdx.x;                 // 128
    const int lane = tid & 31, w = tid >> 5;
    const int bidx = blockIdx.x;                  // 512 blocks
    const int b = bidx >> 8, s = bidx & 255;
    const int n0 = s * CH_NS;

    // --- phase 1: Y = tanh(sum of 8 K-split partials + bias) for 256 points -
    {
        const int gf0 = b * 196608 + n0 * 3;           // flat float base
        const int col0 = (n0 & 1023) * 3;              // bias column base
        for (int o4 = tid; o4 < 192; o4 += 128) {      // full 768-float coverage
            const int o = o4 * 4;
            float4 sacc = *(const float4*)&g_p3[0][gf0 + o];
#pragma unroll
            for (int p = 1; p < 8; p++) {
                const float4 q = *(const float4*)&g_p3[p][gf0 + o];
                sacc.x += q.x; sacc.y += q.y; sacc.z += q.z; sacc.w += q.w;
            }
            const float4 bb = *(const float4*)&bd3[col0 + o];
            sacc.x = tanhf(sacc.x + bb.x);
            sacc.y = tanhf(sacc.y + bb.y);
            sacc.z = tanhf(sacc.z + bb.z);
            sacc.w = tanhf(sacc.w + bb.w);
            *(float4*)&ysc[o] = sacc;
        }
    }
    __syncthreads();
    for (int nn = tid; nn < CH_NS; nn += 128) {
        const float yx = ysc[nn * 3 + 0];
        const float yy = ysc[nn * 3 + 1];
        const float yz = ysc[nn * 3 + 2];
        const float yw = -0.5f * (yx * yx + yy * yy + yz * yz);
        *(float4*)&ys2[nn][0] = make_float4(yx, yx, yy, yy);
        *(float4*)&ys2[nn][4] = make_float4(yz, yz, yw, yw);
    }

    // --- phase 2: per-lane targets, 8 m's as 4 packed pairs ------------------
    u64t sx2[4], sy2[4], sz2[4], hs2[4];
    float mBlo[4], mBhi[4];
    const float* xb = x + (size_t)b * 3072;
#pragma unroll
    for (int g = 0; g < 4; g++) {
        const int m0 = w * 256 + (2 * g) * 32 + lane;
        const int m1 = m0 + 32;
        const float ax = xb[m0 * 3 + 0], ay = xb[m0 * 3 + 1], az = xb[m0 * 3 + 2];
        const float cx = xb[m1 * 3 + 0], cy = xb[m1 * 3 + 1], cz = xb[m1 * 3 + 2];
        sx2[g] = pk2(ax, cx);
        sy2[g] = pk2(ay, cy);
        sz2[g] = pk2(az, cz);
        hs2[g] = pk2(-0.5f * (ax * ax + ay * ay + az * az),
                     -0.5f * (cx * cx + cy * cy + cz * cz));
        mBlo[g] = NEG_INF; mBhi[g] = NEG_INF;
    }
    __syncthreads();

    float sum_n = 0.f;                            // meaningful for tid < 32
    for (int c0 = 0; c0 < CH_NS; c0 += 32) {
#pragma unroll 2
        for (int k = 0; k < 32; k++) {
            const int nn = c0 + k;
            const ulonglong2 yA = *(const ulonglong2*)&ys2[nn][0];  // yx2, yy2
            const ulonglong2 yB = *(const ulonglong2*)&ys2[nn][4];  // yz2, yw2
            float ul[4], uh[4];
#pragma unroll
            for (int g = 0; g < 4; g++) {
                u64t t = fma2(sx2[g], yA.x, hs2[g]);
                t = fma2(sy2[g], yA.y, t);
                t = fma2(sz2[g], yB.x, t);
                t = add2(t, yB.y);
                upk2(ul[g], uh[g], t);
                mBlo[g] = fmaxf(mBlo[g], ul[g]);
                mBhi[g] = fmaxf(mBhi[g], uh[g]);
            }
            mred[k][tid] = fmaxf(fmaxf(fmaxf(ul[0], uh[0]), fmaxf(ul[1], uh[1])),
                                 fmaxf(fmaxf(ul[2], uh[2]), fmaxf(ul[3], uh[3])));
        }
        __syncthreads();
        // cooperative reduce: 4 threads per nn, 32 lanes each
        {
            const int nnl = tid & 31, part = tid >> 5;
            const float* row = &mred[nnl][part * 32];
            float sm = row[0];
#pragma unroll
            for (int j = 1; j < 32; j++) sm = fmaxf(sm, row[j]);
            pw2[nnl][part] = sm;
        }
        __syncthreads();
        if (tid < 32)
            sum_n += fmaxf(fmaxf(pw2[tid][0], pw2[tid][1]),
                           fmaxf(pw2[tid][2], pw2[tid][3]));
        __syncthreads();
    }

    if (tid < 32) {
#pragma unroll
        for (int off = 16; off; off >>= 1)
            sum_n += __shfl_xor_sync(0xffffffffu, sum_n, off);
        if (tid == 0) g_partN[bidx] = sum_n;
    }

    // per-m running max over this block's n-slice -> global
#pragma unroll
    for (int g = 0; g < 4; g++) {
        const int m0 = w * 256 + (2 * g) * 32 + lane;
        atomicMax(&g_umax[b * 1024 + m0],      enc_f(mBlo[g]));
        atomicMax(&g_umax[b * 1024 + m0 + 32], enc_f(mBhi[g]));
    }

    // --- last-block final reduction -----------------------------------------
    __threadfence();
    __syncthreads();
    if (tid == 0) isLast = (atomicAdd(&g_done, 1u) == 511u) ? 1u : 0u;
    __syncthreads();
    if (isLast) {
        float loc = 0.f;
        for (int i = tid; i < 2048; i += 128) loc += dec_f(g_umax[i]);
        for (int i = tid; i < 512; i += 128)  loc += g_partN[i];
#pragma unroll
        for (int off = 16; off; off >>= 1)
            loc += __shfl_xor_sync(0xffffffffu, loc, off);
        if (lane == 0) red2[w] = loc;
        __syncthreads();
        if (tid == 0)
            out[0] = -2.f * ((red2[0] + red2[1]) + (red2[2] + red2[3]));
    }
}

// ---------------------------------------------------------------------------
extern "C" void kernel_launch(void* const* d_in, const int* in_sizes, int n_in,
                              void* d_out, int out_size) {
    const float* x    = (const float*)d_in[0];
    const float* grid = (const float*)d_in[1];
    const float* We1  = (const float*)d_in[2];
    const float* be1  = (const float*)d_in[3];
    const float* We2  = (const float*)d_in[4];
    const float* be2  = (const float*)d_in[5];
    const float* We3  = (const float*)d_in[6];
    const float* be3  = (const float*)d_in[7];
    const float* Wd1  = (const float*)d_in[8];
    const float* bd1  = (const float*)d_in[9];
    const float* Wd2  = (const float*)d_in[10];
    const float* bd2  = (const float*)d_in[11];
    const float* Wd3  = (const float*)d_in[12];
    const float* bd3  = (const float*)d_in[13];
    float* out = (float*)d_out;

    k_e1<<<32, 512>>>(x, We1);
    k_e2<<<16, 128>>>(be1, We2);
    k_dec12<<<128, 128>>>(grid, be2, We3, be3, Wd1, bd1, Wd2, bd2);
    k_dec3<<<768, 128>>>(Wd3);
    k_chamfer<<<512, 128>>>(x, bd3, out);
}